// round 10
// baseline (speedup 1.0000x reference)
#include <cuda_runtime.h>
#include <cstdint>

// ChamferDistance: B=4, N=8192, C=3
// loss = sum_b [ mean_i min_j d2 + mean_j min_i d2 ]
//
// Each d2(i,j) = qs_i + pw_j - 2 q_i.p_j is computed ONCE (4 packed f32x2
// ops per 2 (i,j) pairs) and serves BOTH directions:
//   row-min (per P1 point): one redux.sync.max.u32 on complemented clamped
//     bits (exact bitwise float-min), lane0 -> atomicMax.
//   col-min (per P2 point): private register accumulators, published once.
// PERSISTENT GRID: 592 blocks (4 per SM, exactly one wave) dynamically
// steal (b, qg, rg) work items via an atomic ticket -> no wave
// quantization, tail <= 1 item. Exact-min combining makes the result
// independent of steal order (deterministic).

constexpr int B_      = 4;
constexpr int N_      = 8192;
constexpr int THREADS = 128;            // 4 warps
constexpr int RPT     = 8;              // refs (P2 points) per thread
constexpr int RPW     = 32 * RPT;       // 256 refs per warp
constexpr int RPB     = 4 * RPW;        // 1024 refs per item
constexpr int QPB     = 256;            // P1 queries per item (128 pairs)
constexpr int NQG     = N_ / QPB;       // 32 query groups
constexpr int NRG     = N_ / RPB;       // 8 ref groups
constexpr int NITEMS  = B_ * NQG * NRG; // 1024 work items
constexpr int NBLOCKS = 592;            // 148 SMs x 4 resident
constexpr int NSLOT   = 2 * B_ * N_;    // 65536 min slots (rows then cols)
constexpr int CBLK    = 128;            // combine blocks

__device__ unsigned int g_min[NSLOT];   // 0 loses to any cbits value
__device__ float        g_part[CBLK];
__device__ unsigned int g_work = 0;     // work-steal ticket
__device__ unsigned int g_done = 0;

__device__ __forceinline__ uint64_t pack2(float lo, float hi) {
    uint64_t r;
    asm("mov.b64 %0, {%1, %2};" : "=l"(r) : "f"(lo), "f"(hi));
    return r;
}
__device__ __forceinline__ void unpack2(uint64_t v, float& lo, float& hi) {
    asm("mov.b64 {%0, %1}, %2;" : "=f"(lo), "=f"(hi) : "l"(v));
}
__device__ __forceinline__ uint64_t fma2(uint64_t a, uint64_t b, uint64_t c) {
    uint64_t r;
    asm("fma.rn.f32x2 %0, %1, %2, %3;" : "=l"(r) : "l"(a), "l"(b), "l"(c));
    return r;
}
__device__ __forceinline__ uint64_t add2(uint64_t a, uint64_t b) {
    uint64_t r;
    asm("add.rn.f32x2 %0, %1, %2;" : "=l"(r) : "l"(a), "l"(b));
    return r;
}
// complemented bits of clamped d: uint max over these == float min over d
__device__ __forceinline__ unsigned int cbits(float d) {
    return ~__float_as_uint(fmaxf(d, 0.0f));
}
__device__ __forceinline__ unsigned int redux_max(unsigned int v) {
    unsigned int r;
    asm("redux.sync.max.u32 %0, %1, 0xffffffff;" : "=r"(r) : "r"(v));
    return r;
}

__global__ __launch_bounds__(THREADS, 4)
void chamfer_main(const float* __restrict__ p1, const float* __restrict__ p2)
{
    // Query-pair tiles: sh_a[p]={qx0,qx1,qy0,qy1}, sh_b[p]={qz0,qz1,qs0,qs1}
    __shared__ float4 sh_a[QPB / 2];
    __shared__ float4 sh_b[QPB / 2];
    __shared__ unsigned int sh_item;

    const int tid  = threadIdx.x;
    const int lane = tid & 31;
    const int w    = tid >> 5;

    for (;;) {
        if (tid == 0) sh_item = atomicAdd(&g_work, 1u);
        __syncthreads();             // sh_item visible; prior smem reads done
        const unsigned int item = sh_item;
        if (item >= NITEMS) break;

        const int rg = item & (NRG - 1);          // 0..7
        const int qg = (item >> 3) & (NQG - 1);   // 0..31
        const int b  = item >> 8;                 // 0..3

        const float* __restrict__ q = p1 + (size_t)b * N_ * 3;
        const float* __restrict__ r = p2 + (size_t)b * N_ * 3;
        const int qbase = qg * QPB;

        // Stage 128 query pairs (one per thread)
        {
            const float2* qp = (const float2*)(q + (size_t)(qbase + 2 * tid) * 3);
            const float2 a = qp[0];   // x0 y0
            const float2 c = qp[1];   // z0 x1
            const float2 e = qp[2];   // y1 z1
            const float x0 = a.x, y0 = a.y, z0 = c.x;
            const float x1 = c.y, y1 = e.x, z1 = e.y;
            sh_a[tid] = make_float4(x0, x1, y0, y1);
            sh_b[tid] = make_float4(z0, z1,
                                    x0 * x0 + y0 * y0 + z0 * z0,
                                    x1 * x1 + y1 * y1 + z1 * z1);
        }

        // 8 private refs: -2r replicated-packed, |r|^2 replicated-packed
        uint64_t nrx[RPT], nry[RPT], nrz[RPT], pw2[RPT];
        float    mcol[RPT];
        const int jbase = rg * RPB + w * RPW + lane;
        #pragma unroll
        for (int k = 0; k < RPT; k++) {
            const int j = jbase + k * 32;
            const float rx = r[j * 3 + 0], ry = r[j * 3 + 1], rz = r[j * 3 + 2];
            nrx[k]  = pack2(-2.0f * rx, -2.0f * rx);
            nry[k]  = pack2(-2.0f * ry, -2.0f * ry);
            nrz[k]  = pack2(-2.0f * rz, -2.0f * rz);
            const float rw = rx * rx + ry * ry + rz * rz;
            pw2[k]  = pack2(rw, rw);
            mcol[k] = 1e30f;
        }

        __syncthreads();

        const ulonglong2* __restrict__ sa = (const ulonglong2*)sh_a;
        const ulonglong2* __restrict__ sb = (const ulonglong2*)sh_b;
        const int rowslot = b * N_ + qbase;

        #pragma unroll 2
        for (int p = 0; p < QPB / 2; p++) {
            const ulonglong2 va = sa[p];      // qx2, qy2 (packed query pair)
            const ulonglong2 vb = sb[p];      // qz2, qs2
            const uint64_t qx2 = va.x, qy2 = va.y;
            const uint64_t qz2 = vb.x, qs2 = vb.y;

            // split row accumulators (even/odd k) to halve the fmin chain
            float rla = 1e30f, rlb = 1e30f;
            float rha = 1e30f, rhb = 1e30f;

            #pragma unroll
            for (int k = 0; k < RPT; k += 2) {
                {
                    uint64_t d = fma2(nrx[k], qx2, qs2);
                    d = fma2(nry[k], qy2, d);
                    d = fma2(nrz[k], qz2, d);
                    d = add2(d, pw2[k]);
                    float dl, dh; unpack2(d, dl, dh);
                    mcol[k] = fminf(mcol[k], fminf(dl, dh));
                    rla = fminf(rla, dl);
                    rha = fminf(rha, dh);
                }
                {
                    uint64_t d = fma2(nrx[k + 1], qx2, qs2);
                    d = fma2(nry[k + 1], qy2, d);
                    d = fma2(nrz[k + 1], qz2, d);
                    d = add2(d, pw2[k + 1]);
                    float dl, dh; unpack2(d, dl, dh);
                    mcol[k + 1] = fminf(mcol[k + 1], fminf(dl, dh));
                    rlb = fminf(rlb, dl);
                    rhb = fminf(rhb, dh);
                }
            }

            // warp row-min: one integer redux on complemented clamped bits
            const unsigned int url = redux_max(cbits(fminf(rla, rlb)));
            const unsigned int urh = redux_max(cbits(fminf(rha, rhb)));
            if (lane == 0) {
                atomicMax(&g_min[rowslot + 2 * p],     url);
                atomicMax(&g_min[rowslot + 2 * p + 1], urh);
            }
        }

        // publish col-mins (exact bitwise min across the 32 query groups)
        const int colbase = B_ * N_ + b * N_;
        #pragma unroll
        for (int k = 0; k < RPT; k++)
            atomicMax(&g_min[colbase + jbase + k * 32], cbits(mcol[k]));
    }
}

__global__ __launch_bounds__(256)
void chamfer_combine(float* __restrict__ out)
{
    const int tid = threadIdx.x;
    float s = 0.0f;

    #pragma unroll
    for (int k = 0; k < NSLOT / (CBLK * 256); k++) {
        const int slot = blockIdx.x * (NSLOT / CBLK) + k * 256 + tid;
        const unsigned int u = g_min[slot];
        s += __uint_as_float(~u);         // stored clamped >= 0, exact
        g_min[slot] = 0u;                 // reset for next graph replay
    }

    // Deterministic block reduce
    #pragma unroll
    for (int o = 16; o > 0; o >>= 1)
        s += __shfl_down_sync(0xffffffffu, s, o);
    __shared__ float red[8];
    __shared__ bool  amLast;
    if ((tid & 31) == 0) red[tid >> 5] = s;
    __syncthreads();
    if (tid == 0) {
        float bs = 0.0f;
        #pragma unroll
        for (int wi = 0; wi < 8; wi++) bs += red[wi];
        g_part[blockIdx.x] = bs;
        __threadfence();
        amLast = (atomicAdd(&g_done, 1u) == CBLK - 1);
    }
    __syncthreads();

    if (amLast && tid < 32) {
        float v = g_part[tid] + g_part[tid + 32]
                + g_part[tid + 64] + g_part[tid + 96];
        #pragma unroll
        for (int o = 16; o > 0; o >>= 1)
            v += __shfl_down_sync(0xffffffffu, v, o);
        if (tid == 0) {
            out[0] = v * (1.0f / (float)N_);
            g_done = 0;   // reset for next graph replay
            g_work = 0;   // reset work-steal ticket for next graph replay
        }
    }
}

extern "C" void kernel_launch(void* const* d_in, const int* in_sizes, int n_in,
                              void* d_out, int out_size)
{
    const float* points1 = (const float*)d_in[0];
    const float* points2 = (const float*)d_in[1];
    float* out = (float*)d_out;

    chamfer_main<<<NBLOCKS, THREADS>>>(points1, points2);
    chamfer_combine<<<CBLK, 256>>>(out);
}

// round 11
// speedup vs baseline: 1.0992x; 1.0992x over previous
#include <cuda_runtime.h>
#include <cstdint>

// ChamferDistance: B=4, N=8192, C=3
// loss = sum_b [ mean_i min_j d2 + mean_j min_i d2 ]
//
// Each d2(i,j) = qs_i + pw_j - 2 q_i.p_j computed ONCE (4 packed f32x2 ops
// per 2 pairs), serving BOTH directions. Min accumulation moved off the FP
// pipe: row-mins use integer umin on raw float bits (exact for the strictly
// positive minima here; negatives sort as huge uints = clamped away), col
// mins split half FMNMX / half IMNMX to balance fp vs alu pipes.
// Row warp-reduce: one redux.sync.min.u32. Cross-block combine: atomicMax
// on complemented bits (exact, order-independent -> deterministic).

constexpr int B_      = 4;
constexpr int N_      = 8192;
constexpr int THREADS = 128;            // 4 warps
constexpr int RPT     = 8;              // refs (P2 points) per thread
constexpr int RPW     = 32 * RPT;       // 256 refs per warp
constexpr int RPB     = 4 * RPW;        // 1024 refs per block
constexpr int QPB     = 256;            // P1 queries per block (128 pairs)
constexpr int NQG     = N_ / QPB;       // 32 query groups
constexpr int NRG     = N_ / RPB;       // 8 ref groups
constexpr int NBLOCKS = B_ * NQG * NRG; // 1024
constexpr int NSLOT   = 2 * B_ * N_;    // 65536 min slots (rows then cols)
constexpr int CBLK    = 64;             // combine blocks

__device__ unsigned int g_min[NSLOT];   // 0 loses to any complemented value
__device__ float        g_part[CBLK];
__device__ unsigned int g_done = 0;

__device__ __forceinline__ uint64_t pack2(float lo, float hi) {
    uint64_t r;
    asm("mov.b64 %0, {%1, %2};" : "=l"(r) : "f"(lo), "f"(hi));
    return r;
}
__device__ __forceinline__ void unpack2(uint64_t v, float& lo, float& hi) {
    asm("mov.b64 {%0, %1}, %2;" : "=f"(lo), "=f"(hi) : "l"(v));
}
__device__ __forceinline__ uint64_t fma2(uint64_t a, uint64_t b, uint64_t c) {
    uint64_t r;
    asm("fma.rn.f32x2 %0, %1, %2, %3;" : "=l"(r) : "l"(a), "l"(b), "l"(c));
    return r;
}
__device__ __forceinline__ uint64_t add2(uint64_t a, uint64_t b) {
    uint64_t r;
    asm("add.rn.f32x2 %0, %1, %2;" : "=l"(r) : "l"(a), "l"(b));
    return r;
}
__device__ __forceinline__ unsigned int redux_min(unsigned int v) {
    unsigned int r;
    asm("redux.sync.min.u32 %0, %1, 0xffffffff;" : "=r"(r) : "r"(v));
    return r;
}
__device__ __forceinline__ unsigned int umin2(unsigned int a, unsigned int b) {
    return a < b ? a : b;   // IMNMX.U32 (alu pipe)
}

__global__ __launch_bounds__(THREADS, 4)
void chamfer_main(const float* __restrict__ p1, const float* __restrict__ p2)
{
    const int blk = blockIdx.x;
    const int rg  = blk & (NRG - 1);          // 0..7
    const int qg  = (blk >> 3) & (NQG - 1);   // 0..31
    const int b   = blk >> 8;                 // 0..3

    const float* __restrict__ q = p1 + (size_t)b * N_ * 3;
    const float* __restrict__ r = p2 + (size_t)b * N_ * 3;

    // Query-pair tiles: sh_a[p]={qx0,qx1,qy0,qy1}, sh_b[p]={qz0,qz1,qs0,qs1}
    __shared__ float4 sh_a[QPB / 2];
    __shared__ float4 sh_b[QPB / 2];

    const int tid   = threadIdx.x;
    const int lane  = tid & 31;
    const int w     = tid >> 5;
    const int qbase = qg * QPB;

    // Stage 128 query pairs (one per thread)
    {
        const float2* qp = (const float2*)(q + (size_t)(qbase + 2 * tid) * 3);
        const float2 a = qp[0];   // x0 y0
        const float2 c = qp[1];   // z0 x1
        const float2 e = qp[2];   // y1 z1
        const float x0 = a.x, y0 = a.y, z0 = c.x;
        const float x1 = c.y, y1 = e.x, z1 = e.y;
        sh_a[tid] = make_float4(x0, x1, y0, y1);
        sh_b[tid] = make_float4(z0, z1,
                                x0 * x0 + y0 * y0 + z0 * z0,
                                x1 * x1 + y1 * y1 + z1 * z1);
    }

    // 8 private refs: -2r replicated-packed, |r|^2 replicated-packed
    uint64_t nrx[RPT], nry[RPT], nrz[RPT], pw2[RPT];
    float        mcf[RPT / 2];   // col-min accumulators, float half (fma pipe)
    unsigned int mcu[RPT / 2];   // col-min accumulators, integer half (alu pipe)
    const int jbase = rg * RPB + w * RPW + lane;
    #pragma unroll
    for (int k = 0; k < RPT; k++) {
        const int j = jbase + k * 32;
        const float rx = r[j * 3 + 0], ry = r[j * 3 + 1], rz = r[j * 3 + 2];
        nrx[k] = pack2(-2.0f * rx, -2.0f * rx);
        nry[k] = pack2(-2.0f * ry, -2.0f * ry);
        nrz[k] = pack2(-2.0f * rz, -2.0f * rz);
        const float rw = rx * rx + ry * ry + rz * rz;
        pw2[k] = pack2(rw, rw);
    }
    #pragma unroll
    for (int k = 0; k < RPT / 2; k++) { mcf[k] = 1e30f; mcu[k] = 0xffffffffu; }

    __syncthreads();

    const ulonglong2* __restrict__ sa = (const ulonglong2*)sh_a;
    const ulonglong2* __restrict__ sb = (const ulonglong2*)sh_b;
    const int rowslot = b * N_ + qbase;

    #pragma unroll 2
    for (int p = 0; p < QPB / 2; p++) {
        const ulonglong2 va = sa[p];      // qx2, qy2 (packed query pair)
        const ulonglong2 vb = sb[p];      // qz2, qs2
        const uint64_t qx2 = va.x, qy2 = va.y;
        const uint64_t qz2 = vb.x, qs2 = vb.y;

        // integer row accumulators (split to relax the dependency chain)
        unsigned int rla = 0xffffffffu, rlb = 0xffffffffu;
        unsigned int rha = 0xffffffffu, rhb = 0xffffffffu;

        #pragma unroll
        for (int k = 0; k < RPT; k += 2) {
            {   // even k: col-min on FP pipe
                uint64_t d = fma2(nrx[k], qx2, qs2);
                d = fma2(nry[k], qy2, d);
                d = fma2(nrz[k], qz2, d);
                d = add2(d, pw2[k]);
                float dl, dh; unpack2(d, dl, dh);
                mcf[k >> 1] = fminf(mcf[k >> 1], fminf(dl, dh));
                const unsigned int udl = __float_as_uint(dl);
                const unsigned int udh = __float_as_uint(dh);
                rla = umin2(rla, udl);
                rha = umin2(rha, udh);
            }
            {   // odd k: col-min on ALU pipe
                uint64_t d = fma2(nrx[k + 1], qx2, qs2);
                d = fma2(nry[k + 1], qy2, d);
                d = fma2(nrz[k + 1], qz2, d);
                d = add2(d, pw2[k + 1]);
                float dl, dh; unpack2(d, dl, dh);
                const unsigned int udl = __float_as_uint(dl);
                const unsigned int udh = __float_as_uint(dh);
                mcu[k >> 1] = umin2(mcu[k >> 1], umin2(udl, udh));
                rlb = umin2(rlb, udl);
                rhb = umin2(rhb, udh);
            }
        }

        // warp row-min: single integer redux on raw bits
        const unsigned int url = redux_min(umin2(rla, rlb));
        const unsigned int urh = redux_min(umin2(rha, rhb));
        if (lane == 0) {
            atomicMax(&g_min[rowslot + 2 * p],     ~url);
            atomicMax(&g_min[rowslot + 2 * p + 1], ~urh);
        }
    }

    // publish col-mins (exact bitwise min across the 32 query groups)
    const int colbase = B_ * N_ + b * N_;
    #pragma unroll
    for (int k = 0; k < RPT; k++) {
        const unsigned int bits = (k & 1)
            ? mcu[k >> 1]
            : __float_as_uint(mcf[k >> 1]);
        atomicMax(&g_min[colbase + jbase + k * 32], ~bits);
    }
}

__global__ __launch_bounds__(256)
void chamfer_combine(float* __restrict__ out)
{
    const int tid = threadIdx.x;
    float s = 0.0f;

    #pragma unroll
    for (int k = 0; k < NSLOT / (CBLK * 256); k++) {
        const int slot = blockIdx.x * (NSLOT / CBLK) + k * 256 + tid;
        const unsigned int u = g_min[slot];
        s += fmaxf(__uint_as_float(~u), 0.0f);   // clamp like the reference
        g_min[slot] = 0u;                        // reset for next graph replay
    }

    // Deterministic block reduce
    #pragma unroll
    for (int o = 16; o > 0; o >>= 1)
        s += __shfl_down_sync(0xffffffffu, s, o);
    __shared__ float red[8];
    __shared__ bool  amLast;
    if ((tid & 31) == 0) red[tid >> 5] = s;
    __syncthreads();
    if (tid == 0) {
        float bs = 0.0f;
        #pragma unroll
        for (int wi = 0; wi < 8; wi++) bs += red[wi];
        g_part[blockIdx.x] = bs;
        __threadfence();
        amLast = (atomicAdd(&g_done, 1u) == CBLK - 1);
    }
    __syncthreads();

    if (amLast && tid < 32) {
        float v = g_part[tid] + g_part[tid + 32];
        #pragma unroll
        for (int o = 16; o > 0; o >>= 1)
            v += __shfl_down_sync(0xffffffffu, v, o);
        if (tid == 0) {
            out[0] = v * (1.0f / (float)N_);
            g_done = 0;   // reset for next graph replay
        }
    }
}

extern "C" void kernel_launch(void* const* d_in, const int* in_sizes, int n_in,
                              void* d_out, int out_size)
{
    const float* points1 = (const float*)d_in[0];
    const float* points2 = (const float*)d_in[1];
    float* out = (float*)d_out;

    chamfer_main<<<NBLOCKS, THREADS>>>(points1, points2);
    chamfer_combine<<<CBLK, 256>>>(out);
}